// round 15
// baseline (speedup 1.0000x reference)
#include <cuda_runtime.h>
#include <cuda_fp16.h>
#include <math.h>

#define BATCH 8
#define SEQ   4096
#define EMB   768
#define HD    64
#define PADF  68    // float smem row stride (x tiles)
#define STH   72    // half smem row stride (64 data + 8 pad), 144B, 16B-aligned

// fp16 scratch
__device__ __half g_q [BATCH * SEQ * HD];   // [b][t][d], pre-scaled by 0.125*log2(e)
__device__ __half g_k [BATCH * SEQ * HD];   // [b][t][d]
__device__ __half g_vT[BATCH * HD * SEQ];   // [b][d][t]
__device__ __half g_wT[3 * HD * EMB];       // [m][n][k]

__device__ __forceinline__ void mma_f16(float c[4],
                                        unsigned a0, unsigned a1, unsigned a2, unsigned a3,
                                        unsigned b0, unsigned b1) {
    asm("mma.sync.aligned.m16n8k16.row.col.f32.f16.f16.f32 "
        "{%0,%1,%2,%3}, {%4,%5,%6,%7}, {%8,%9}, {%0,%1,%2,%3};"
        : "+f"(c[0]), "+f"(c[1]), "+f"(c[2]), "+f"(c[3])
        : "r"(a0), "r"(a1), "r"(a2), "r"(a3), "r"(b0), "r"(b1));
}

__device__ __forceinline__ void ldmat4(unsigned& r0, unsigned& r1, unsigned& r2, unsigned& r3,
                                       unsigned addr) {
    asm volatile("ldmatrix.sync.aligned.m8n8.x4.shared.b16 {%0,%1,%2,%3}, [%4];"
                 : "=r"(r0), "=r"(r1), "=r"(r2), "=r"(r3) : "r"(addr));
}

__device__ __forceinline__ void cp16(void* dst, const void* src) {
    unsigned d = (unsigned)__cvta_generic_to_shared(dst);
    asm volatile("cp.async.cg.shared.global [%0], [%1], 16;" :: "r"(d), "l"(src));
}
__device__ __forceinline__ void cp_commit() { asm volatile("cp.async.commit_group;"); }
__device__ __forceinline__ void cp_wait0()  { asm volatile("cp.async.wait_group 0;" ::: "memory"); }
__device__ __forceinline__ void cp_wait1()  { asm volatile("cp.async.wait_group 1;" ::: "memory"); }

__device__ __forceinline__ float ex2f(float x) {
    float y;
    asm("ex2.approx.ftz.f32 %0, %1;" : "=f"(y) : "f"(x));
    return y;
}
__device__ __forceinline__ unsigned h2exp2(unsigned x) {
    unsigned y;
    asm("ex2.approx.f16x2 %0, %1;" : "=r"(y) : "r"(x));
    return y;
}
__device__ __forceinline__ unsigned h2u(__half2 h) { return *(unsigned*)&h; }

// ---------------------------------------------------------------------------
// Kernel 0: transpose + fp16-convert weights: g_wT[m][n][k]
// ---------------------------------------------------------------------------
__global__ __launch_bounds__(256) void prep_w(
    const float* __restrict__ Wq, const float* __restrict__ Wk, const float* __restrict__ Wv)
{
    int i = blockIdx.x * 256 + threadIdx.x;
    if (i >= 3 * EMB * HD) return;
    int m = i / (EMB * HD);
    int r = (i / HD) % EMB;
    int c = i & (HD - 1);
    const float* W = (m == 0) ? Wq : (m == 1) ? Wk : Wv;
    g_wT[(m * HD + c) * EMB + r] = __float2half(W[r * HD + c]);
}

// ---------------------------------------------------------------------------
// Kernel 1: fused QKV projection, fp16 MMA, cp.async double-buffered.
// NEW: x converted to fp16 ONCE per chunk (shared xh buffer) instead of 3x
// redundantly per matrix warp-group; A fragments via ldmatrix from xh.
// 192 threads = 6 warps; warp w: matrix (w>>1), rows 32*(w&1)..+32.
// ---------------------------------------------------------------------------
#define XBYTES (64 * PADF * 4)             // 17408 fp32 x stage (16B-aligned)
#define WBYTES (3 * 64 * STH * 2)          // 27648
#define QSTAGE (XBYTES + WBYTES)           // 45056
#define XHOFF  (2 * QSTAGE)                // fp16 x buffer (single, rebuilt per chunk)
#define QKV_SMEM (XHOFF + 64 * STH * 2)    // 99328

__global__ __launch_bounds__(192, 2) void qkv_kernel(
    const float* __restrict__ x,
    const float* __restrict__ bq, const float* __restrict__ bk, const float* __restrict__ bv)
{
    extern __shared__ char smc[];

    const int tid  = threadIdx.x;
    const int lane = tid & 31;
    const int w    = tid >> 5;         // 0..5
    const int mat  = w >> 1;           // 0=q, 1=k, 2=v
    const int half = w & 1;            // row half: rows 32*half .. 32*half+31
    const int g    = lane >> 2;
    const int tg   = lane & 3;
    const int row0 = blockIdx.x * 64;

    const float* bias = (mat == 0) ? bq : (mat == 1) ? bk : bv;

    auto issue = [&](int kt, int st) {
        float*  xs = (float*)(smc + st * QSTAGE);
        __half* ws = (__half*)(smc + st * QSTAGE + XBYTES);
        for (int i = tid; i < 64 * 16; i += 192) {
            int r = i >> 4, q = i & 15;
            cp16(&xs[r * PADF + q * 4], &x[(size_t)(row0 + r) * EMB + kt * 64 + q * 4]);
        }
        for (int i = tid; i < 3 * 64 * 8; i += 192) {
            int r = i >> 3, q = i & 7;
            cp16(&ws[r * STH + q * 8], &g_wT[(size_t)r * EMB + kt * 64 + q * 8]);
        }
        cp_commit();
    };

    const int grp = lane >> 3, rr = lane & 7;
    // B-operand ldmatrix offset: row-half = grp>>1, k-half = grp&1
    const unsigned thoffB = (unsigned)((rr + (grp >> 1) * 8) * (STH * 2) + (grp & 1) * 16);
    // A-operand ldmatrix offset: row-half = grp&1, k-half = grp>>1
    const unsigned thoffA = (unsigned)((rr + (grp & 1) * 8) * (STH * 2) + (grp >> 1) * 16);
    const unsigned smb = (unsigned)__cvta_generic_to_shared(smc);

    __half* xh = (__half*)(smc + XHOFF);

    float acc[2][8][4];
    #pragma unroll
    for (int h = 0; h < 2; h++)
        #pragma unroll
        for (int j = 0; j < 8; j++)
            #pragma unroll
            for (int i = 0; i < 4; i++) acc[h][j][i] = 0.f;

    issue(0, 0);
    int st = 0;
    for (int kt = 0; kt < EMB / 64; kt++) {
        cp_wait0();
        __syncthreads();                    // tile ready; prior xh reads done
        if (kt + 1 < EMB / 64) issue(kt + 1, st ^ 1);

        // cooperative fp32->fp16 conversion of the x tile (once, not 3x)
        float* xs = (float*)(smc + st * QSTAGE);
        for (int i = tid; i < 64 * 32; i += 192) {
            int r = i >> 5, c = (i & 31) * 2;
            float2 f = *(const float2*)&xs[r * PADF + c];
            *(__half2*)&xh[r * STH + c] = __floats2half2_rn(f.x, f.y);
        }
        __syncthreads();                    // xh ready

        const unsigned wsa = smb + (unsigned)(st * QSTAGE + XBYTES + mat * (64 * STH * 2)) + thoffB;
        const unsigned xha = smb + (unsigned)(XHOFF + 32 * half * (STH * 2)) + thoffA;

        #pragma unroll
        for (int s = 0; s < 4; s++) {
            unsigned a0[4], a1[4];
            ldmat4(a0[0], a0[1], a0[2], a0[3], xha + (unsigned)(s * 32));
            ldmat4(a1[0], a1[1], a1[2], a1[3], xha + (unsigned)(16 * STH * 2 + s * 32));
            #pragma unroll
            for (int p = 0; p < 4; p++) {
                unsigned b0, b1, b2, b3;
                ldmat4(b0, b1, b2, b3, wsa + (unsigned)(p * (16 * STH * 2) + s * 32));
                mma_f16(acc[0][2 * p],     a0[0], a0[1], a0[2], a0[3], b0, b1);
                mma_f16(acc[0][2 * p + 1], a0[0], a0[1], a0[2], a0[3], b2, b3);
                mma_f16(acc[1][2 * p],     a1[0], a1[1], a1[2], a1[3], b0, b1);
                mma_f16(acc[1][2 * p + 1], a1[0], a1[1], a1[2], a1[3], b2, b3);
            }
        }
        st ^= 1;
    }

    const float QSCALE = 0.125f * 1.4426950408889634f;   // D^-0.5 * log2(e)
    #pragma unroll
    for (int h = 0; h < 2; h++) {
        #pragma unroll
        for (int j = 0; j < 8; j++) {
            int col = j * 8 + 2 * tg;
            float b0 = bias[col], b1 = bias[col + 1];
            int r0 = row0 + 32 * half + 16 * h + g;
            float v00 = acc[h][j][0] + b0, v01 = acc[h][j][1] + b1;
            float v10 = acc[h][j][2] + b0, v11 = acc[h][j][3] + b1;
            if (mat == 0) { v00 *= QSCALE; v01 *= QSCALE; v10 *= QSCALE; v11 *= QSCALE; }
            if (mat == 2) {
                int b = r0 >> 12, t = r0 & (SEQ - 1);
                size_t base = (size_t)b * HD * SEQ;
                g_vT[base + (size_t)col       * SEQ + t]     = __float2half(v00);
                g_vT[base + (size_t)(col + 1) * SEQ + t]     = __float2half(v01);
                g_vT[base + (size_t)col       * SEQ + t + 8] = __float2half(v10);
                g_vT[base + (size_t)(col + 1) * SEQ + t + 8] = __float2half(v11);
            } else {
                __half* outp = (mat == 0) ? g_q : g_k;
                *(__half2*)&outp[(size_t)r0 * HD + col]       = __floats2half2_rn(v00, v01);
                *(__half2*)&outp[(size_t)(r0 + 8) * HD + col] = __floats2half2_rn(v10, v11);
            }
        }
    }
}

// ---------------------------------------------------------------------------
// Kernel 2: causal flash attention (exact R14 best version).
// ---------------------------------------------------------------------------
#define ASTAGE (2 * 64 * STH)    // halves per stage (K tile + V tile) = 18432 B

__global__ __launch_bounds__(128, 2) void attn_kernel(float* __restrict__ out)
{
    extern __shared__ __half smh[];

    const int tid  = threadIdx.x;
    const int lane = tid & 31;
    const int w    = tid >> 5;         // 0..3, query rows 32w..32w+31
    const int g    = lane >> 2;
    const int tg   = lane & 3;
    const int b    = blockIdx.y;

    const int x  = blockIdx.x;         // 0..31
    const int r_ = x & 3;
    const int p_ = (5 * (x >> 2)) & 7;
    const int a_ = r_ * 4 + (p_ >> 1);
    const int qt = (p_ & 1) ? (31 - a_) : a_;

    const int nkt = 2 * qt + 2;        // 64-key tiles

    const __half* qg  = g_q  + ((size_t)b * SEQ + qt * 128) * HD;
    const __half* kg  = g_k  + (size_t)b * SEQ * HD;
    const __half* vTg = g_vT + (size_t)b * HD * SEQ;

    auto issue = [&](int kt, int stg) {
        __half* ks = smh + stg * ASTAGE;
        __half* vs = ks + 64 * STH;
        for (int i = tid; i < 64 * 8; i += 128) {
            int r = i >> 3, q = i & 7;
            cp16(&ks[r * STH + q * 8], &kg[(size_t)(kt * 64 + r) * HD + q * 8]);
            cp16(&vs[r * STH + q * 8], &vTg[(size_t)r * SEQ + kt * 64 + q * 8]);
        }
        cp_commit();
    };

    issue(0, 0);
    issue(1 < nkt ? 1 : 0, 1);

    unsigned qa[2][4][4];
    #pragma unroll
    for (int h = 0; h < 2; h++) {
        #pragma unroll
        for (int s = 0; s < 4; s++) {
            const __half* base = &qg[(size_t)(32 * w + 16 * h + g) * HD + 16 * s + 2 * tg];
            qa[h][s][0] = *(const unsigned*)&base[0];
            qa[h][s][1] = *(const unsigned*)&base[8 * HD];
            qa[h][s][2] = *(const unsigned*)&base[8];
            qa[h][s][3] = *(const unsigned*)&base[8 * HD + 8];
        }
    }

    const int grp = lane >> 3, rr = lane & 7;
    const unsigned thoff = (unsigned)((rr + (grp >> 1) * 8) * (STH * 2) + (grp & 1) * 16);
    const unsigned ones_b = (g == 0) ? 0x3C003C00u : 0u;
    const unsigned smbase = (unsigned)__cvta_generic_to_shared(smh);

    float O[2][9][4];
    #pragma unroll
    for (int h = 0; h < 2; h++)
        #pragma unroll
        for (int j = 0; j < 9; j++)
            #pragma unroll
            for (int i = 0; i < 4; i++) O[h][j][i] = 0.f;
    float m0[2] = {-INFINITY, -INFINITY}, m1[2] = {-INFINITY, -INFINITY};

    for (int kt = 0; kt < nkt; kt++) {
        cp_wait1();
        __syncthreads();
        if (kt + 2 < nkt) issue(kt + 2, (kt + 2) % 3);

        const unsigned ksa = smbase + (unsigned)((kt % 3) * ASTAGE * 2);
        const unsigned vsa = ksa + 64 * STH * 2;

        float S[2][8][4];
        #pragma unroll
        for (int h = 0; h < 2; h++)
            #pragma unroll
            for (int j = 0; j < 8; j++)
                #pragma unroll
                for (int i = 0; i < 4; i++) S[h][j][i] = 0.f;

        #pragma unroll
        for (int s = 0; s < 4; s++) {
            #pragma unroll
            for (int p = 0; p < 4; p++) {
                unsigned b0, b1, b2, b3;
                ldmat4(b0, b1, b2, b3, ksa + (unsigned)(p * (16 * STH * 2) + s * 32) + thoff);
                mma_f16(S[0][2 * p],     qa[0][s][0], qa[0][s][1], qa[0][s][2], qa[0][s][3], b0, b1);
                mma_f16(S[0][2 * p + 1], qa[0][s][0], qa[0][s][1], qa[0][s][2], qa[0][s][3], b2, b3);
                mma_f16(S[1][2 * p],     qa[1][s][0], qa[1][s][1], qa[1][s][2], qa[1][s][3], b0, b1);
                mma_f16(S[1][2 * p + 1], qa[1][s][0], qa[1][s][1], qa[1][s][2], qa[1][s][3], b2, b3);
            }
        }

        if (kt >= 2 * qt) {
            int kb = (kt - 2 * qt) * 64;
            #pragma unroll
            for (int h = 0; h < 2; h++) {
                int r0 = 32 * w + 16 * h + g, r1 = r0 + 8;
                #pragma unroll
                for (int j = 0; j < 8; j++) {
                    int c0 = kb + j * 8 + 2 * tg, c1 = c0 + 1;
                    if (c0 > r0) S[h][j][0] = -10000.f;
                    if (c1 > r0) S[h][j][1] = -10000.f;
                    if (c0 > r1) S[h][j][2] = -10000.f;
                    if (c1 > r1) S[h][j][3] = -10000.f;
                }
            }
        }

        float tmax0[2], tmax1[2];
        #pragma unroll
        for (int h = 0; h < 2; h++) {
            float t0 = -INFINITY, t1 = -INFINITY;
            #pragma unroll
            for (int j = 0; j < 8; j++) {
                t0 = fmaxf(t0, fmaxf(S[h][j][0], S[h][j][1]));
                t1 = fmaxf(t1, fmaxf(S[h][j][2], S[h][j][3]));
            }
            t0 = fmaxf(t0, __shfl_xor_sync(0xffffffffu, t0, 1));
            t0 = fmaxf(t0, __shfl_xor_sync(0xffffffffu, t0, 2));
            t1 = fmaxf(t1, __shfl_xor_sync(0xffffffffu, t1, 1));
            t1 = fmaxf(t1, __shfl_xor_sync(0xffffffffu, t1, 2));
            tmax0[h] = t0; tmax1[h] = t1;
        }

        bool stable = (tmax0[0] <= m0[0]) & (tmax1[0] <= m1[0]) &
                      (tmax0[1] <= m0[1]) & (tmax1[1] <= m1[1]);
        if (!__all_sync(0xffffffffu, stable)) {
            #pragma unroll
            for (int h = 0; h < 2; h++) {
                float mn0 = fmaxf(m0[h], tmax0[h]), mn1 = fmaxf(m1[h], tmax1[h]);
                float al0 = ex2f(m0[h] - mn0), al1 = ex2f(m1[h] - mn1);
                m0[h] = mn0; m1[h] = mn1;
                #pragma unroll
                for (int j = 0; j < 9; j++) {
                    O[h][j][0] *= al0; O[h][j][1] *= al0;
                    O[h][j][2] *= al1; O[h][j][3] *= al1;
                }
            }
        }

        unsigned pk[2][4][4];
        #pragma unroll
        for (int h = 0; h < 2; h++) {
            #pragma unroll
            for (int s = 0; s < 4; s++) {
                pk[h][s][0] = h2exp2(h2u(__floats2half2_rn(S[h][2*s][0]   - m0[h], S[h][2*s][1]   - m0[h])));
                pk[h][s][1] = h2exp2(h2u(__floats2half2_rn(S[h][2*s][2]   - m1[h], S[h][2*s][3]   - m1[h])));
                pk[h][s][2] = h2exp2(h2u(__floats2half2_rn(S[h][2*s+1][0] - m0[h], S[h][2*s+1][1] - m0[h])));
                pk[h][s][3] = h2exp2(h2u(__floats2half2_rn(S[h][2*s+1][2] - m1[h], S[h][2*s+1][3] - m1[h])));
            }
        }

        #pragma unroll
        for (int s = 0; s < 4; s++) {
            #pragma unroll
            for (int p = 0; p < 4; p++) {
                unsigned b0, b1, b2, b3;
                ldmat4(b0, b1, b2, b3, vsa + (unsigned)(p * (16 * STH * 2) + s * 32) + thoff);
                mma_f16(O[0][2 * p],     pk[0][s][0], pk[0][s][1], pk[0][s][2], pk[0][s][3], b0, b1);
                mma_f16(O[0][2 * p + 1], pk[0][s][0], pk[0][s][1], pk[0][s][2], pk[0][s][3], b2, b3);
                mma_f16(O[1][2 * p],     pk[1][s][0], pk[1][s][1], pk[1][s][2], pk[1][s][3], b0, b1);
                mma_f16(O[1][2 * p + 1], pk[1][s][0], pk[1][s][1], pk[1][s][2], pk[1][s][3], b2, b3);
            }
            mma_f16(O[0][8], pk[0][s][0], pk[0][s][1], pk[0][s][2], pk[0][s][3], ones_b, ones_b);
            mma_f16(O[1][8], pk[1][s][0], pk[1][s][1], pk[1][s][2], pk[1][s][3], ones_b, ones_b);
        }
    }

    #pragma unroll
    for (int h = 0; h < 2; h++) {
        float l0 = __shfl_sync(0xffffffffu, O[h][8][0], lane & 28);
        float l1 = __shfl_sync(0xffffffffu, O[h][8][2], lane & 28);
        float inv0 = 1.0f / l0, inv1 = 1.0f / l1;
        int r0 = qt * 128 + 32 * w + 16 * h + g;
        #pragma unroll
        for (int j = 0; j < 8; j++) {
            int col = j * 8 + 2 * tg;
            *(float2*)&out[((size_t)b * SEQ + r0) * HD + col] =
                make_float2(O[h][j][0] * inv0, O[h][j][1] * inv0);
            *(float2*)&out[((size_t)b * SEQ + r0 + 8) * HD + col] =
                make_float2(O[h][j][2] * inv1, O[h][j][3] * inv1);
        }
    }
}

extern "C" void kernel_launch(void* const* d_in, const int* in_sizes, int n_in,
                              void* d_out, int out_size)
{
    const float* x  = (const float*)d_in[0];
    const float* Wq = (const float*)d_in[1];
    const float* bq = (const float*)d_in[2];
    const float* Wk = (const float*)d_in[3];
    const float* bk = (const float*)d_in[4];
    const float* Wv = (const float*)d_in[5];
    const float* bv = (const float*)d_in[6];
    float* out = (float*)d_out;

    const int attn_smem = 3 * ASTAGE * (int)sizeof(__half);        // 55296
    cudaFuncSetAttribute(qkv_kernel,  cudaFuncAttributeMaxDynamicSharedMemorySize, QKV_SMEM);
    cudaFuncSetAttribute(attn_kernel, cudaFuncAttributeMaxDynamicSharedMemorySize, attn_smem);

    prep_w<<<(3 * EMB * HD + 255) / 256, 256>>>(Wq, Wk, Wv);
    qkv_kernel<<<(BATCH * SEQ) / 64, 192, QKV_SMEM>>>(x, bq, bk, bv);

    dim3 grid(SEQ / 128, BATCH);
    attn_kernel<<<grid, 128, attn_smem>>>(out);
}

// round 16
// speedup vs baseline: 1.0812x; 1.0812x over previous
#include <cuda_runtime.h>
#include <cuda_fp16.h>
#include <math.h>

#define BATCH 8
#define SEQ   4096
#define EMB   768
#define HD    64
#define PADF  68    // float smem row stride (x tiles)
#define STH   72    // half smem row stride (64 data + 8 pad), 144B, 16B-aligned

// fp16 scratch
__device__ __half g_q [BATCH * SEQ * HD];   // [b][t][d], pre-scaled by 0.125*log2(e)
__device__ __half g_k [BATCH * SEQ * HD];   // [b][t][d]
__device__ __half g_vT[BATCH * HD * SEQ];   // [b][d][t]
__device__ __half g_wT[3 * HD * EMB];       // [m][n][k]
__device__ float  g_nmax[2][BATCH];         // max row-norm^2 of q-hat / k per batch

__device__ __forceinline__ void mma_f16(float c[4],
                                        unsigned a0, unsigned a1, unsigned a2, unsigned a3,
                                        unsigned b0, unsigned b1) {
    asm("mma.sync.aligned.m16n8k16.row.col.f32.f16.f16.f32 "
        "{%0,%1,%2,%3}, {%4,%5,%6,%7}, {%8,%9}, {%0,%1,%2,%3};"
        : "+f"(c[0]), "+f"(c[1]), "+f"(c[2]), "+f"(c[3])
        : "r"(a0), "r"(a1), "r"(a2), "r"(a3), "r"(b0), "r"(b1));
}

__device__ __forceinline__ void ldmat4(unsigned& r0, unsigned& r1, unsigned& r2, unsigned& r3,
                                       unsigned addr) {
    asm volatile("ldmatrix.sync.aligned.m8n8.x4.shared.b16 {%0,%1,%2,%3}, [%4];"
                 : "=r"(r0), "=r"(r1), "=r"(r2), "=r"(r3) : "r"(addr));
}

__device__ __forceinline__ void cp16(void* dst, const void* src) {
    unsigned d = (unsigned)__cvta_generic_to_shared(dst);
    asm volatile("cp.async.cg.shared.global [%0], [%1], 16;" :: "r"(d), "l"(src));
}
__device__ __forceinline__ void cp_commit() { asm volatile("cp.async.commit_group;"); }
__device__ __forceinline__ void cp_wait0()  { asm volatile("cp.async.wait_group 0;" ::: "memory"); }
__device__ __forceinline__ void cp_wait1()  { asm volatile("cp.async.wait_group 1;" ::: "memory"); }

__device__ __forceinline__ unsigned h2exp2(unsigned x) {
    unsigned y;
    asm("ex2.approx.f16x2 %0, %1;" : "=r"(y) : "r"(x));
    return y;
}
__device__ __forceinline__ unsigned h2u(__half2 h) { return *(unsigned*)&h; }

// ---------------------------------------------------------------------------
// Kernel 0: transpose + fp16-convert weights; also zero the norm maxima.
// ---------------------------------------------------------------------------
__global__ __launch_bounds__(256) void prep_w(
    const float* __restrict__ Wq, const float* __restrict__ Wk, const float* __restrict__ Wv)
{
    if (blockIdx.x == 0 && threadIdx.x < 2 * BATCH)
        ((float*)g_nmax)[threadIdx.x] = 0.f;
    int i = blockIdx.x * 256 + threadIdx.x;
    if (i >= 3 * EMB * HD) return;
    int m = i / (EMB * HD);
    int r = (i / HD) % EMB;
    int c = i & (HD - 1);
    const float* W = (m == 0) ? Wq : (m == 1) ? Wk : Wv;
    g_wT[(m * HD + c) * EMB + r] = __float2half(W[r * HD + c]);
}

// ---------------------------------------------------------------------------
// Kernel 1: fused QKV projection (R14 version) + per-batch row-norm maxima.
// 192 threads = 6 warps; warp w: matrix (w>>1), rows 32*(w&1)..+32.
// ---------------------------------------------------------------------------
#define XBYTES (64 * PADF * 4)             // 17408 (16B-aligned)
#define WBYTES (3 * 64 * STH * 2)          // 27648
#define QSTAGE (XBYTES + WBYTES)           // 45056

__global__ __launch_bounds__(192, 2) void qkv_kernel(
    const float* __restrict__ x,
    const float* __restrict__ bq, const float* __restrict__ bk, const float* __restrict__ bv)
{
    extern __shared__ char smc[];

    const int tid  = threadIdx.x;
    const int lane = tid & 31;
    const int w    = tid >> 5;         // 0..5
    const int mat  = w >> 1;           // 0=q, 1=k, 2=v
    const int half = w & 1;
    const int g    = lane >> 2;
    const int tg   = lane & 3;
    const int row0 = blockIdx.x * 64;

    const float* bias = (mat == 0) ? bq : (mat == 1) ? bk : bv;

    auto issue = [&](int kt, int st) {
        float*  xs = (float*)(smc + st * QSTAGE);
        __half* ws = (__half*)(smc + st * QSTAGE + XBYTES);
        for (int i = tid; i < 64 * 16; i += 192) {
            int r = i >> 4, q = i & 15;
            cp16(&xs[r * PADF + q * 4], &x[(size_t)(row0 + r) * EMB + kt * 64 + q * 4]);
        }
        for (int i = tid; i < 3 * 64 * 8; i += 192) {
            int r = i >> 3, q = i & 7;
            cp16(&ws[r * STH + q * 8], &g_wT[(size_t)r * EMB + kt * 64 + q * 8]);
        }
        cp_commit();
    };

    const int grp = lane >> 3, rr = lane & 7;
    const unsigned thoff = (unsigned)((rr + (grp >> 1) * 8) * (STH * 2) + (grp & 1) * 16);
    const unsigned smb = (unsigned)__cvta_generic_to_shared(smc);

    float acc[2][8][4];
    #pragma unroll
    for (int h = 0; h < 2; h++)
        #pragma unroll
        for (int j = 0; j < 8; j++)
            #pragma unroll
            for (int i = 0; i < 4; i++) acc[h][j][i] = 0.f;

    issue(0, 0);
    int st = 0;
    for (int kt = 0; kt < EMB / 64; kt++) {
        cp_wait0();
        __syncthreads();
        if (kt + 1 < EMB / 64) issue(kt + 1, st ^ 1);

        float* xs = (float*)(smc + st * QSTAGE);
        const unsigned wsa = smb + (unsigned)(st * QSTAGE + XBYTES + mat * (64 * STH * 2)) + thoff;

        unsigned aa[2][4][4];
        #pragma unroll
        for (int h = 0; h < 2; h++) {
            #pragma unroll
            for (int s = 0; s < 4; s++) {
                const float* base = &xs[(32 * half + 16 * h + g) * PADF + 16 * s + 2 * tg];
                float2 f0 = *(const float2*)&base[0];
                float2 f1 = *(const float2*)&base[8 * PADF];
                float2 f2 = *(const float2*)&base[8];
                float2 f3 = *(const float2*)&base[8 * PADF + 8];
                aa[h][s][0] = h2u(__floats2half2_rn(f0.x, f0.y));
                aa[h][s][1] = h2u(__floats2half2_rn(f1.x, f1.y));
                aa[h][s][2] = h2u(__floats2half2_rn(f2.x, f2.y));
                aa[h][s][3] = h2u(__floats2half2_rn(f3.x, f3.y));
            }
        }
        #pragma unroll
        for (int s = 0; s < 4; s++) {
            #pragma unroll
            for (int p = 0; p < 4; p++) {
                unsigned b0, b1, b2, b3;
                ldmat4(b0, b1, b2, b3, wsa + (unsigned)(p * (16 * STH * 2) + s * 32));
                mma_f16(acc[0][2 * p],     aa[0][s][0], aa[0][s][1], aa[0][s][2], aa[0][s][3], b0, b1);
                mma_f16(acc[0][2 * p + 1], aa[0][s][0], aa[0][s][1], aa[0][s][2], aa[0][s][3], b2, b3);
                mma_f16(acc[1][2 * p],     aa[1][s][0], aa[1][s][1], aa[1][s][2], aa[1][s][3], b0, b1);
                mma_f16(acc[1][2 * p + 1], aa[1][s][0], aa[1][s][1], aa[1][s][2], aa[1][s][3], b2, b3);
            }
        }
        st ^= 1;
    }

    const float QSCALE = 0.125f * 1.4426950408889634f;   // D^-0.5 * log2(e)
    const int bidx = row0 >> 12;
    float nrm[2][2] = {{0.f, 0.f}, {0.f, 0.f}};          // [h][row-half] row-norm^2 partials

    #pragma unroll
    for (int h = 0; h < 2; h++) {
        #pragma unroll
        for (int j = 0; j < 8; j++) {
            int col = j * 8 + 2 * tg;
            float b0 = bias[col], b1 = bias[col + 1];
            int r0 = row0 + 32 * half + 16 * h + g;
            float v00 = acc[h][j][0] + b0, v01 = acc[h][j][1] + b1;
            float v10 = acc[h][j][2] + b0, v11 = acc[h][j][3] + b1;
            if (mat == 0) { v00 *= QSCALE; v01 *= QSCALE; v10 *= QSCALE; v11 *= QSCALE; }
            if (mat < 2) {
                nrm[h][0] += v00 * v00 + v01 * v01;
                nrm[h][1] += v10 * v10 + v11 * v11;
            }
            if (mat == 2) {
                int b = r0 >> 12, t = r0 & (SEQ - 1);
                size_t base = (size_t)b * HD * SEQ;
                g_vT[base + (size_t)col       * SEQ + t]     = __float2half(v00);
                g_vT[base + (size_t)(col + 1) * SEQ + t]     = __float2half(v01);
                g_vT[base + (size_t)col       * SEQ + t + 8] = __float2half(v10);
                g_vT[base + (size_t)(col + 1) * SEQ + t + 8] = __float2half(v11);
            } else {
                __half* outp = (mat == 0) ? g_q : g_k;
                *(__half2*)&outp[(size_t)r0 * HD + col]       = __floats2half2_rn(v00, v01);
                *(__half2*)&outp[(size_t)(r0 + 8) * HD + col] = __floats2half2_rn(v10, v11);
            }
        }
    }

    // per-batch max row-norm^2 of q-hat (mat 0) and k (mat 1)
    if (mat < 2) {
        float mx = 0.f;
        #pragma unroll
        for (int h = 0; h < 2; h++)
            #pragma unroll
            for (int rh = 0; rh < 2; rh++) {
                float v = nrm[h][rh];
                v += __shfl_xor_sync(0xffffffffu, v, 1);
                v += __shfl_xor_sync(0xffffffffu, v, 2);
                mx = fmaxf(mx, v);
            }
        mx = fmaxf(mx, __shfl_xor_sync(0xffffffffu, mx, 4));
        mx = fmaxf(mx, __shfl_xor_sync(0xffffffffu, mx, 8));
        mx = fmaxf(mx, __shfl_xor_sync(0xffffffffu, mx, 16));
        if (lane == 0)
            atomicMax((int*)&g_nmax[mat][bidx], __float_as_int(mx));
    }
}

// ---------------------------------------------------------------------------
// Kernel 2: causal flash attention — NO online softmax. Uses the global
// Cauchy-Schwarz bound B >= max S, so P = 2^(S-B) directly; O and l share the
// 2^-B scale which cancels at normalization. Tile body: S MMAs -> pack/ex2 ->
// PV MMAs; no max reduction, no shuffles, no rescale.
// ---------------------------------------------------------------------------
#define ASTAGE (2 * 64 * STH)    // halves per stage (K tile + V tile) = 18432 B

__global__ __launch_bounds__(128, 2) void attn_kernel(float* __restrict__ out)
{
    extern __shared__ __half smh[];

    const int tid  = threadIdx.x;
    const int lane = tid & 31;
    const int w    = tid >> 5;         // 0..3, query rows 32w..32w+31
    const int g    = lane >> 2;
    const int tg   = lane & 3;
    const int b    = blockIdx.y;

    const int x  = blockIdx.x;         // 0..31
    const int r_ = x & 3;
    const int p_ = (5 * (x >> 2)) & 7;
    const int a_ = r_ * 4 + (p_ >> 1);
    const int qt = (p_ & 1) ? (31 - a_) : a_;

    const int nkt = 2 * qt + 2;        // 64-key tiles

    const float B = sqrtf(g_nmax[0][b] * g_nmax[1][b]);   // bound on |S| (log2 units)

    const __half* qg  = g_q  + ((size_t)b * SEQ + qt * 128) * HD;
    const __half* kg  = g_k  + (size_t)b * SEQ * HD;
    const __half* vTg = g_vT + (size_t)b * HD * SEQ;

    auto issue = [&](int kt, int stg) {
        __half* ks = smh + stg * ASTAGE;
        __half* vs = ks + 64 * STH;
        for (int i = tid; i < 64 * 8; i += 128) {
            int r = i >> 3, q = i & 7;
            cp16(&ks[r * STH + q * 8], &kg[(size_t)(kt * 64 + r) * HD + q * 8]);
            cp16(&vs[r * STH + q * 8], &vTg[(size_t)r * SEQ + kt * 64 + q * 8]);
        }
        cp_commit();
    };

    issue(0, 0);
    issue(1 < nkt ? 1 : 0, 1);

    unsigned qa[2][4][4];
    #pragma unroll
    for (int h = 0; h < 2; h++) {
        #pragma unroll
        for (int s = 0; s < 4; s++) {
            const __half* base = &qg[(size_t)(32 * w + 16 * h + g) * HD + 16 * s + 2 * tg];
            qa[h][s][0] = *(const unsigned*)&base[0];
            qa[h][s][1] = *(const unsigned*)&base[8 * HD];
            qa[h][s][2] = *(const unsigned*)&base[8];
            qa[h][s][3] = *(const unsigned*)&base[8 * HD + 8];
        }
    }

    const int grp = lane >> 3, rr = lane & 7;
    const unsigned thoff = (unsigned)((rr + (grp >> 1) * 8) * (STH * 2) + (grp & 1) * 16);
    const unsigned ones_b = (g == 0) ? 0x3C003C00u : 0u;
    const unsigned smbase = (unsigned)__cvta_generic_to_shared(smh);

    float O[2][9][4];
    #pragma unroll
    for (int h = 0; h < 2; h++)
        #pragma unroll
        for (int j = 0; j < 9; j++)
            #pragma unroll
            for (int i = 0; i < 4; i++) O[h][j][i] = 0.f;

    for (int kt = 0; kt < nkt; kt++) {
        cp_wait1();
        __syncthreads();
        if (kt + 2 < nkt) issue(kt + 2, (kt + 2) % 3);

        const unsigned ksa = smbase + (unsigned)((kt % 3) * ASTAGE * 2);
        const unsigned vsa = ksa + 64 * STH * 2;

        // S = Q @ K^T (log2 domain)
        float S[2][8][4];
        #pragma unroll
        for (int h = 0; h < 2; h++)
            #pragma unroll
            for (int j = 0; j < 8; j++)
                #pragma unroll
                for (int i = 0; i < 4; i++) S[h][j][i] = 0.f;

        #pragma unroll
        for (int s = 0; s < 4; s++) {
            #pragma unroll
            for (int p = 0; p < 4; p++) {
                unsigned b0, b1, b2, b3;
                ldmat4(b0, b1, b2, b3, ksa + (unsigned)(p * (16 * STH * 2) + s * 32) + thoff);
                mma_f16(S[0][2 * p],     qa[0][s][0], qa[0][s][1], qa[0][s][2], qa[0][s][3], b0, b1);
                mma_f16(S[0][2 * p + 1], qa[0][s][0], qa[0][s][1], qa[0][s][2], qa[0][s][3], b2, b3);
                mma_f16(S[1][2 * p],     qa[1][s][0], qa[1][s][1], qa[1][s][2], qa[1][s][3], b0, b1);
                mma_f16(S[1][2 * p + 1], qa[1][s][0], qa[1][s][1], qa[1][s][2], qa[1][s][3], b2, b3);
            }
        }

        // causal mask — the last two key tiles intersect the diagonal
        if (kt >= 2 * qt) {
            int kb = (kt - 2 * qt) * 64;
            #pragma unroll
            for (int h = 0; h < 2; h++) {
                int r0 = 32 * w + 16 * h + g, r1 = r0 + 8;
                #pragma unroll
                for (int j = 0; j < 8; j++) {
                    int c0 = kb + j * 8 + 2 * tg, c1 = c0 + 1;
                    if (c0 > r0) S[h][j][0] = -10000.f;
                    if (c1 > r0) S[h][j][1] = -10000.f;
                    if (c0 > r1) S[h][j][2] = -10000.f;
                    if (c1 > r1) S[h][j][3] = -10000.f;
                }
            }
        }

        // P = 2^(S - B): fp32 subtract -> f16x2 pack -> ex2.approx.f16x2
        unsigned pk[2][4][4];
        #pragma unroll
        for (int h = 0; h < 2; h++) {
            #pragma unroll
            for (int s = 0; s < 4; s++) {
                pk[h][s][0] = h2exp2(h2u(__floats2half2_rn(S[h][2*s][0]   - B, S[h][2*s][1]   - B)));
                pk[h][s][1] = h2exp2(h2u(__floats2half2_rn(S[h][2*s][2]   - B, S[h][2*s][3]   - B)));
                pk[h][s][2] = h2exp2(h2u(__floats2half2_rn(S[h][2*s+1][0] - B, S[h][2*s+1][1] - B)));
                pk[h][s][3] = h2exp2(h2u(__floats2half2_rn(S[h][2*s+1][2] - B, S[h][2*s+1][3] - B)));
            }
        }

        // O += P @ V for both halves (shared V fragments); l via ones column
        #pragma unroll
        for (int s = 0; s < 4; s++) {
            #pragma unroll
            for (int p = 0; p < 4; p++) {
                unsigned b0, b1, b2, b3;
                ldmat4(b0, b1, b2, b3, vsa + (unsigned)(p * (16 * STH * 2) + s * 32) + thoff);
                mma_f16(O[0][2 * p],     pk[0][s][0], pk[0][s][1], pk[0][s][2], pk[0][s][3], b0, b1);
                mma_f16(O[0][2 * p + 1], pk[0][s][0], pk[0][s][1], pk[0][s][2], pk[0][s][3], b2, b3);
                mma_f16(O[1][2 * p],     pk[1][s][0], pk[1][s][1], pk[1][s][2], pk[1][s][3], b0, b1);
                mma_f16(O[1][2 * p + 1], pk[1][s][0], pk[1][s][1], pk[1][s][2], pk[1][s][3], b2, b3);
            }
            mma_f16(O[0][8], pk[0][s][0], pk[0][s][1], pk[0][s][2], pk[0][s][3], ones_b, ones_b);
            mma_f16(O[1][8], pk[1][s][0], pk[1][s][1], pk[1][s][2], pk[1][s][3], ones_b, ones_b);
        }
    }

    #pragma unroll
    for (int h = 0; h < 2; h++) {
        float l0 = __shfl_sync(0xffffffffu, O[h][8][0], lane & 28);
        float l1 = __shfl_sync(0xffffffffu, O[h][8][2], lane & 28);
        float inv0 = 1.0f / l0, inv1 = 1.0f / l1;
        int r0 = qt * 128 + 32 * w + 16 * h + g;
        #pragma unroll
        for (int j = 0; j < 8; j++) {
            int col = j * 8 + 2 * tg;
            *(float2*)&out[((size_t)b * SEQ + r0) * HD + col] =
                make_float2(O[h][j][0] * inv0, O[h][j][1] * inv0);
            *(float2*)&out[((size_t)b * SEQ + r0 + 8) * HD + col] =
                make_float2(O[h][j][2] * inv1, O[h][j][3] * inv1);
        }
    }
}

extern "C" void kernel_launch(void* const* d_in, const int* in_sizes, int n_in,
                              void* d_out, int out_size)
{
    const float* x  = (const float*)d_in[0];
    const float* Wq = (const float*)d_in[1];
    const float* bq = (const float*)d_in[2];
    const float* Wk = (const float*)d_in[3];
    const float* bk = (const float*)d_in[4];
    const float* Wv = (const float*)d_in[5];
    const float* bv = (const float*)d_in[6];
    float* out = (float*)d_out;

    const int qkv_smem  = 2 * QSTAGE;                              // 90112
    const int attn_smem = 3 * ASTAGE * (int)sizeof(__half);        // 55296
    cudaFuncSetAttribute(qkv_kernel,  cudaFuncAttributeMaxDynamicSharedMemorySize, qkv_smem);
    cudaFuncSetAttribute(attn_kernel, cudaFuncAttributeMaxDynamicSharedMemorySize, attn_smem);

    prep_w<<<(3 * EMB * HD + 255) / 256, 256>>>(Wq, Wk, Wv);
    qkv_kernel<<<(BATCH * SEQ) / 64, 192, qkv_smem>>>(x, bq, bk, bv);

    dim3 grid(SEQ / 128, BATCH);
    attn_kernel<<<grid, 128, attn_smem>>>(out);
}

// round 17
// speedup vs baseline: 1.1211x; 1.0368x over previous
#include <cuda_runtime.h>
#include <cuda_fp16.h>
#include <math.h>

#define BATCH 8
#define SEQ   4096
#define EMB   768
#define HD    64
#define PADF  68    // float smem row stride (x tiles)
#define STH   72    // half smem row stride (64 data + 8 pad), 144B, 16B-aligned

// fp16 scratch
__device__ __half g_q [BATCH * SEQ * HD];   // [b][t][d], pre-scaled by 0.125*log2(e)
__device__ __half g_k [BATCH * SEQ * HD];   // [b][t][d]
__device__ __half g_vT[BATCH * HD * SEQ];   // [b][d][t]
__device__ __half g_wT[3 * HD * EMB];       // [m][n][k]
__device__ float  g_nmax[2][BATCH];         // max row-norm^2 of q-hat / k per batch

__device__ __forceinline__ void mma_f16(float c[4],
                                        unsigned a0, unsigned a1, unsigned a2, unsigned a3,
                                        unsigned b0, unsigned b1) {
    asm("mma.sync.aligned.m16n8k16.row.col.f32.f16.f16.f32 "
        "{%0,%1,%2,%3}, {%4,%5,%6,%7}, {%8,%9}, {%0,%1,%2,%3};"
        : "+f"(c[0]), "+f"(c[1]), "+f"(c[2]), "+f"(c[3])
        : "r"(a0), "r"(a1), "r"(a2), "r"(a3), "r"(b0), "r"(b1));
}

__device__ __forceinline__ void ldmat4(unsigned& r0, unsigned& r1, unsigned& r2, unsigned& r3,
                                       unsigned addr) {
    asm volatile("ldmatrix.sync.aligned.m8n8.x4.shared.b16 {%0,%1,%2,%3}, [%4];"
                 : "=r"(r0), "=r"(r1), "=r"(r2), "=r"(r3) : "r"(addr));
}

__device__ __forceinline__ void cp16(void* dst, const void* src) {
    unsigned d = (unsigned)__cvta_generic_to_shared(dst);
    asm volatile("cp.async.cg.shared.global [%0], [%1], 16;" :: "r"(d), "l"(src));
}
__device__ __forceinline__ void cp_commit() { asm volatile("cp.async.commit_group;"); }
__device__ __forceinline__ void cp_wait0()  { asm volatile("cp.async.wait_group 0;" ::: "memory"); }
__device__ __forceinline__ void cp_wait1()  { asm volatile("cp.async.wait_group 1;" ::: "memory"); }

__device__ __forceinline__ unsigned h2exp2(unsigned x) {
    unsigned y;
    asm("ex2.approx.f16x2 %0, %1;" : "=r"(y) : "r"(x));
    return y;
}
__device__ __forceinline__ unsigned h2u(__half2 h) { return *(unsigned*)&h; }

// ---------------------------------------------------------------------------
// Kernel 0: transpose + fp16-convert weights; also zero the norm maxima.
// ---------------------------------------------------------------------------
__global__ __launch_bounds__(256) void prep_w(
    const float* __restrict__ Wq, const float* __restrict__ Wk, const float* __restrict__ Wv)
{
    if (blockIdx.x == 0 && threadIdx.x < 2 * BATCH)
        ((float*)g_nmax)[threadIdx.x] = 0.f;
    int i = blockIdx.x * 256 + threadIdx.x;
    if (i >= 3 * EMB * HD) return;
    int m = i / (EMB * HD);
    int r = (i / HD) % EMB;
    int c = i & (HD - 1);
    const float* W = (m == 0) ? Wq : (m == 1) ? Wk : Wv;
    g_wT[(m * HD + c) * EMB + r] = __float2half(W[r * HD + c]);
}

// ---------------------------------------------------------------------------
// Kernel 1: fused QKV projection — warps partitioned by ROWS only.
// 128 threads = 4 warps; warp w owns rows 16w..16w+15 and computes ALL THREE
// matrices: A fragments built once (no 3x redundancy), B via ldmatrix,
// 192 MMAs per warp per chunk. cp.async double-buffered.
// ---------------------------------------------------------------------------
#define XBYTES (64 * PADF * 4)             // 17408 (16B-aligned)
#define WBYTES (3 * 64 * STH * 2)          // 27648
#define QSTAGE (XBYTES + WBYTES)           // 45056

__global__ __launch_bounds__(128, 2) void qkv_kernel(
    const float* __restrict__ x,
    const float* __restrict__ bq, const float* __restrict__ bk, const float* __restrict__ bv)
{
    extern __shared__ char smc[];

    const int tid  = threadIdx.x;
    const int lane = tid & 31;
    const int w    = tid >> 5;         // 0..3, rows 16w..16w+15
    const int g    = lane >> 2;
    const int tg   = lane & 3;
    const int row0 = blockIdx.x * 64;

    auto issue = [&](int kt, int st) {
        float*  xs = (float*)(smc + st * QSTAGE);
        __half* ws = (__half*)(smc + st * QSTAGE + XBYTES);
        for (int i = tid; i < 64 * 16; i += 128) {
            int r = i >> 4, q = i & 15;
            cp16(&xs[r * PADF + q * 4], &x[(size_t)(row0 + r) * EMB + kt * 64 + q * 4]);
        }
        for (int i = tid; i < 3 * 64 * 8; i += 128) {
            int r = i >> 3, q = i & 7;
            cp16(&ws[r * STH + q * 8], &g_wT[(size_t)r * EMB + kt * 64 + q * 8]);
        }
        cp_commit();
    };

    const int grp = lane >> 3, rr = lane & 7;
    const unsigned thoff = (unsigned)((rr + (grp >> 1) * 8) * (STH * 2) + (grp & 1) * 16);
    const unsigned smb = (unsigned)__cvta_generic_to_shared(smc);

    float acc[3][8][4];
    #pragma unroll
    for (int m = 0; m < 3; m++)
        #pragma unroll
        for (int j = 0; j < 8; j++)
            #pragma unroll
            for (int i = 0; i < 4; i++) acc[m][j][i] = 0.f;

    issue(0, 0);
    int st = 0;
    for (int kt = 0; kt < EMB / 64; kt++) {
        cp_wait0();
        __syncthreads();
        if (kt + 1 < EMB / 64) issue(kt + 1, st ^ 1);

        float* xs = (float*)(smc + st * QSTAGE);
        const unsigned wbase = smb + (unsigned)(st * QSTAGE + XBYTES) + thoff;

        // A fragments for this warp's 16 rows (built ONCE, reused by all mats)
        unsigned a[4][4];
        #pragma unroll
        for (int s = 0; s < 4; s++) {
            const float* base = &xs[(16 * w + g) * PADF + 16 * s + 2 * tg];
            float2 f0 = *(const float2*)&base[0];
            float2 f1 = *(const float2*)&base[8 * PADF];
            float2 f2 = *(const float2*)&base[8];
            float2 f3 = *(const float2*)&base[8 * PADF + 8];
            a[s][0] = h2u(__floats2half2_rn(f0.x, f0.y));
            a[s][1] = h2u(__floats2half2_rn(f1.x, f1.y));
            a[s][2] = h2u(__floats2half2_rn(f2.x, f2.y));
            a[s][3] = h2u(__floats2half2_rn(f3.x, f3.y));
        }
        #pragma unroll
        for (int s = 0; s < 4; s++) {
            #pragma unroll
            for (int p = 0; p < 4; p++) {
                #pragma unroll
                for (int m = 0; m < 3; m++) {
                    unsigned b0, b1, b2, b3;
                    ldmat4(b0, b1, b2, b3,
                           wbase + (unsigned)(m * (64 * STH * 2) + p * (16 * STH * 2) + s * 32));
                    mma_f16(acc[m][2 * p],     a[s][0], a[s][1], a[s][2], a[s][3], b0, b1);
                    mma_f16(acc[m][2 * p + 1], a[s][0], a[s][1], a[s][2], a[s][3], b2, b3);
                }
            }
        }
        st ^= 1;
    }

    const float QSCALE = 0.125f * 1.4426950408889634f;   // D^-0.5 * log2(e)
    const int bidx = row0 >> 12;
    float nq[2] = {0.f, 0.f}, nk[2] = {0.f, 0.f};        // row-norm^2 partials (rows g, g+8)

    #pragma unroll
    for (int m = 0; m < 3; m++) {
        const float* bias = (m == 0) ? bq : (m == 1) ? bk : bv;
        #pragma unroll
        for (int j = 0; j < 8; j++) {
            int col = j * 8 + 2 * tg;
            float b0 = bias[col], b1 = bias[col + 1];
            int r0 = row0 + 16 * w + g;
            float v00 = acc[m][j][0] + b0, v01 = acc[m][j][1] + b1;
            float v10 = acc[m][j][2] + b0, v11 = acc[m][j][3] + b1;
            if (m == 0) { v00 *= QSCALE; v01 *= QSCALE; v10 *= QSCALE; v11 *= QSCALE; }
            if (m == 0) {
                nq[0] += v00 * v00 + v01 * v01;
                nq[1] += v10 * v10 + v11 * v11;
            } else if (m == 1) {
                nk[0] += v00 * v00 + v01 * v01;
                nk[1] += v10 * v10 + v11 * v11;
            }
            if (m == 2) {
                int b = r0 >> 12, t = r0 & (SEQ - 1);
                size_t base = (size_t)b * HD * SEQ;
                g_vT[base + (size_t)col       * SEQ + t]     = __float2half(v00);
                g_vT[base + (size_t)(col + 1) * SEQ + t]     = __float2half(v01);
                g_vT[base + (size_t)col       * SEQ + t + 8] = __float2half(v10);
                g_vT[base + (size_t)(col + 1) * SEQ + t + 8] = __float2half(v11);
            } else {
                __half* outp = (m == 0) ? g_q : g_k;
                *(__half2*)&outp[(size_t)r0 * HD + col]       = __floats2half2_rn(v00, v01);
                *(__half2*)&outp[(size_t)(r0 + 8) * HD + col] = __floats2half2_rn(v10, v11);
            }
        }
    }

    // per-batch max row-norm^2 of q-hat and k
    #pragma unroll
    for (int m = 0; m < 2; m++) {
        float mx = 0.f;
        #pragma unroll
        for (int rh = 0; rh < 2; rh++) {
            float v = (m == 0) ? nq[rh] : nk[rh];
            v += __shfl_xor_sync(0xffffffffu, v, 1);
            v += __shfl_xor_sync(0xffffffffu, v, 2);
            mx = fmaxf(mx, v);
        }
        mx = fmaxf(mx, __shfl_xor_sync(0xffffffffu, mx, 4));
        mx = fmaxf(mx, __shfl_xor_sync(0xffffffffu, mx, 8));
        mx = fmaxf(mx, __shfl_xor_sync(0xffffffffu, mx, 16));
        if (lane == 0)
            atomicMax((int*)&g_nmax[m][bidx], __float_as_int(mx));
    }
}

// ---------------------------------------------------------------------------
// Kernel 2: causal flash attention (exact R16 best version — bound softmax).
// ---------------------------------------------------------------------------
#define ASTAGE (2 * 64 * STH)    // halves per stage (K tile + V tile) = 18432 B

__global__ __launch_bounds__(128, 2) void attn_kernel(float* __restrict__ out)
{
    extern __shared__ __half smh[];

    const int tid  = threadIdx.x;
    const int lane = tid & 31;
    const int w    = tid >> 5;         // 0..3, query rows 32w..32w+31
    const int g    = lane >> 2;
    const int tg   = lane & 3;
    const int b    = blockIdx.y;

    const int x  = blockIdx.x;         // 0..31
    const int r_ = x & 3;
    const int p_ = (5 * (x >> 2)) & 7;
    const int a_ = r_ * 4 + (p_ >> 1);
    const int qt = (p_ & 1) ? (31 - a_) : a_;

    const int nkt = 2 * qt + 2;        // 64-key tiles

    const float B = sqrtf(g_nmax[0][b] * g_nmax[1][b]);   // bound on |S| (log2 units)

    const __half* qg  = g_q  + ((size_t)b * SEQ + qt * 128) * HD;
    const __half* kg  = g_k  + (size_t)b * SEQ * HD;
    const __half* vTg = g_vT + (size_t)b * HD * SEQ;

    auto issue = [&](int kt, int stg) {
        __half* ks = smh + stg * ASTAGE;
        __half* vs = ks + 64 * STH;
        for (int i = tid; i < 64 * 8; i += 128) {
            int r = i >> 3, q = i & 7;
            cp16(&ks[r * STH + q * 8], &kg[(size_t)(kt * 64 + r) * HD + q * 8]);
            cp16(&vs[r * STH + q * 8], &vTg[(size_t)r * SEQ + kt * 64 + q * 8]);
        }
        cp_commit();
    };

    issue(0, 0);
    issue(1 < nkt ? 1 : 0, 1);

    unsigned qa[2][4][4];
    #pragma unroll
    for (int h = 0; h < 2; h++) {
        #pragma unroll
        for (int s = 0; s < 4; s++) {
            const __half* base = &qg[(size_t)(32 * w + 16 * h + g) * HD + 16 * s + 2 * tg];
            qa[h][s][0] = *(const unsigned*)&base[0];
            qa[h][s][1] = *(const unsigned*)&base[8 * HD];
            qa[h][s][2] = *(const unsigned*)&base[8];
            qa[h][s][3] = *(const unsigned*)&base[8 * HD + 8];
        }
    }

    const int grp = lane >> 3, rr = lane & 7;
    const unsigned thoff = (unsigned)((rr + (grp >> 1) * 8) * (STH * 2) + (grp & 1) * 16);
    const unsigned ones_b = (g == 0) ? 0x3C003C00u : 0u;
    const unsigned smbase = (unsigned)__cvta_generic_to_shared(smh);

    float O[2][9][4];
    #pragma unroll
    for (int h = 0; h < 2; h++)
        #pragma unroll
        for (int j = 0; j < 9; j++)
            #pragma unroll
            for (int i = 0; i < 4; i++) O[h][j][i] = 0.f;

    for (int kt = 0; kt < nkt; kt++) {
        cp_wait1();
        __syncthreads();
        if (kt + 2 < nkt) issue(kt + 2, (kt + 2) % 3);

        const unsigned ksa = smbase + (unsigned)((kt % 3) * ASTAGE * 2);
        const unsigned vsa = ksa + 64 * STH * 2;

        float S[2][8][4];
        #pragma unroll
        for (int h = 0; h < 2; h++)
            #pragma unroll
            for (int j = 0; j < 8; j++)
                #pragma unroll
                for (int i = 0; i < 4; i++) S[h][j][i] = 0.f;

        #pragma unroll
        for (int s = 0; s < 4; s++) {
            #pragma unroll
            for (int p = 0; p < 4; p++) {
                unsigned b0, b1, b2, b3;
                ldmat4(b0, b1, b2, b3, ksa + (unsigned)(p * (16 * STH * 2) + s * 32) + thoff);
                mma_f16(S[0][2 * p],     qa[0][s][0], qa[0][s][1], qa[0][s][2], qa[0][s][3], b0, b1);
                mma_f16(S[0][2 * p + 1], qa[0][s][0], qa[0][s][1], qa[0][s][2], qa[0][s][3], b2, b3);
                mma_f16(S[1][2 * p],     qa[1][s][0], qa[1][s][1], qa[1][s][2], qa[1][s][3], b0, b1);
                mma_f16(S[1][2 * p + 1], qa[1][s][0], qa[1][s][1], qa[1][s][2], qa[1][s][3], b2, b3);
            }
        }

        if (kt >= 2 * qt) {
            int kb = (kt - 2 * qt) * 64;
            #pragma unroll
            for (int h = 0; h < 2; h++) {
                int r0 = 32 * w + 16 * h + g, r1 = r0 + 8;
                #pragma unroll
                for (int j = 0; j < 8; j++) {
                    int c0 = kb + j * 8 + 2 * tg, c1 = c0 + 1;
                    if (c0 > r0) S[h][j][0] = -10000.f;
                    if (c1 > r0) S[h][j][1] = -10000.f;
                    if (c0 > r1) S[h][j][2] = -10000.f;
                    if (c1 > r1) S[h][j][3] = -10000.f;
                }
            }
        }

        unsigned pk[2][4][4];
        #pragma unroll
        for (int h = 0; h < 2; h++) {
            #pragma unroll
            for (int s = 0; s < 4; s++) {
                pk[h][s][0] = h2exp2(h2u(__floats2half2_rn(S[h][2*s][0]   - B, S[h][2*s][1]   - B)));
                pk[h][s][1] = h2exp2(h2u(__floats2half2_rn(S[h][2*s][2]   - B, S[h][2*s][3]   - B)));
                pk[h][s][2] = h2exp2(h2u(__floats2half2_rn(S[h][2*s+1][0] - B, S[h][2*s+1][1] - B)));
                pk[h][s][3] = h2exp2(h2u(__floats2half2_rn(S[h][2*s+1][2] - B, S[h][2*s+1][3] - B)));
            }
        }

        #pragma unroll
        for (int s = 0; s < 4; s++) {
            #pragma unroll
            for (int p = 0; p < 4; p++) {
                unsigned b0, b1, b2, b3;
                ldmat4(b0, b1, b2, b3, vsa + (unsigned)(p * (16 * STH * 2) + s * 32) + thoff);
                mma_f16(O[0][2 * p],     pk[0][s][0], pk[0][s][1], pk[0][s][2], pk[0][s][3], b0, b1);
                mma_f16(O[0][2 * p + 1], pk[0][s][0], pk[0][s][1], pk[0][s][2], pk[0][s][3], b2, b3);
                mma_f16(O[1][2 * p],     pk[1][s][0], pk[1][s][1], pk[1][s][2], pk[1][s][3], b0, b1);
                mma_f16(O[1][2 * p + 1], pk[1][s][0], pk[1][s][1], pk[1][s][2], pk[1][s][3], b2, b3);
            }
            mma_f16(O[0][8], pk[0][s][0], pk[0][s][1], pk[0][s][2], pk[0][s][3], ones_b, ones_b);
            mma_f16(O[1][8], pk[1][s][0], pk[1][s][1], pk[1][s][2], pk[1][s][3], ones_b, ones_b);
        }
    }

    #pragma unroll
    for (int h = 0; h < 2; h++) {
        float l0 = __shfl_sync(0xffffffffu, O[h][8][0], lane & 28);
        float l1 = __shfl_sync(0xffffffffu, O[h][8][2], lane & 28);
        float inv0 = 1.0f / l0, inv1 = 1.0f / l1;
        int r0 = qt * 128 + 32 * w + 16 * h + g;
        #pragma unroll
        for (int j = 0; j < 8; j++) {
            int col = j * 8 + 2 * tg;
            *(float2*)&out[((size_t)b * SEQ + r0) * HD + col] =
                make_float2(O[h][j][0] * inv0, O[h][j][1] * inv0);
            *(float2*)&out[((size_t)b * SEQ + r0 + 8) * HD + col] =
                make_float2(O[h][j][2] * inv1, O[h][j][3] * inv1);
        }
    }
}

extern "C" void kernel_launch(void* const* d_in, const int* in_sizes, int n_in,
                              void* d_out, int out_size)
{
    const float* x  = (const float*)d_in[0];
    const float* Wq = (const float*)d_in[1];
    const float* bq = (const float*)d_in[2];
    const float* Wk = (const float*)d_in[3];
    const float* bk = (const float*)d_in[4];
    const float* Wv = (const float*)d_in[5];
    const float* bv = (const float*)d_in[6];
    float* out = (float*)d_out;

    const int qkv_smem  = 2 * QSTAGE;                              // 90112
    const int attn_smem = 3 * ASTAGE * (int)sizeof(__half);        // 55296
    cudaFuncSetAttribute(qkv_kernel,  cudaFuncAttributeMaxDynamicSharedMemorySize, qkv_smem);
    cudaFuncSetAttribute(attn_kernel, cudaFuncAttributeMaxDynamicSharedMemorySize, attn_smem);

    prep_w<<<(3 * EMB * HD + 255) / 256, 256>>>(Wq, Wk, Wv);
    qkv_kernel<<<(BATCH * SEQ) / 64, 128, qkv_smem>>>(x, bq, bk, bv);

    dim3 grid(SEQ / 128, BATCH);
    attn_kernel<<<grid, 128, attn_smem>>>(out);
}